// round 6
// baseline (speedup 1.0000x reference)
#include <cuda_runtime.h>

#define FULLMASK 0xffffffffu
#define C_IN 32
#define C_OUT 64
#define K_TAPS 8
#define NMAX 2001024
#define BSHIFT 10                    // 1024 output rows per bucket
#define BROWS (1 << BSHIFT)
#define NBMAX ((NMAX >> BSHIFT) + 2)
#define NBINSMAX (NBMAX * 8)
#define BATCH 8
#define IDXMASK 0x1FFFFF

// ---------------- device scratch ----------------
__device__ float g_sum[C_IN];
__device__ float g_sq[C_IN];
__device__ float g_scale[C_IN];
__device__ float g_shift[C_IN];
__device__ int   g_hist2[NBINSMAX];
__device__ int   g_base2[NBINSMAX + 1];
__device__ int   g_cur2[NBINSMAX];
__device__ int   g_perm[NMAX];
__device__ int   g_ticket;

// ---------------- PTX helpers ----------------
__device__ __forceinline__ unsigned long long fma2(unsigned long long a,
                                                   unsigned long long b,
                                                   unsigned long long c) {
    unsigned long long d;
    asm("fma.rn.f32x2 %0, %1, %2, %3;" : "=l"(d) : "l"(a), "l"(b), "l"(c));
    return d;
}
__device__ __forceinline__ unsigned long long pk(float lo, float hi) {
    unsigned long long d;
    asm("mov.b64 %0, {%1, %2};" : "=l"(d) : "f"(lo), "f"(hi));
    return d;
}
__device__ __forceinline__ void upk(unsigned long long v, float& lo, float& hi) {
    asm("mov.b64 {%0, %1}, %2;" : "=f"(lo), "=f"(hi) : "l"(v));
}
__device__ __forceinline__ void red_add_v2(float* p, float a, float b) {
    asm volatile("red.global.add.v2.f32 [%0], {%1, %2};"
                 :: "l"(p), "f"(a), "f"(b) : "memory");
}

// ---------------- BN stats + 2-D (bucket,tap) histogram ----------------
// g_hist2 / g_sum / g_sq are zero on entry (zero-init at load; re-zeroed by
// k_scanmid on every call -> replay-safe).
__global__ void __launch_bounds__(256) k_pre(
    const float4* __restrict__ f4, long nf4,
    const int4* __restrict__ off4, const int4* __restrict__ oix4,
    int nq, int n) {
    long tid = blockIdx.x * (long)blockDim.x + threadIdx.x;
    long S = (long)gridDim.x * blockDim.x;   // 4*S % 32 == 0

    float s0 = 0, s1 = 0, s2 = 0, s3 = 0;
    float q0 = 0, q1 = 0, q2 = 0, q3 = 0;
    for (long i = tid; i < nf4; i += S) {
        float4 v = f4[i];
        s0 += v.x; q0 = fmaf(v.x, v.x, q0);
        s1 += v.y; q1 = fmaf(v.y, v.y, q1);
        s2 += v.z; q2 = fmaf(v.z, v.z, q2);
        s3 += v.w; q3 = fmaf(v.w, v.w, q3);
    }
    int c0 = (int)((tid * 4) & 31);

    __shared__ float ss[C_IN], sq[C_IN];
    int t = threadIdx.x;
    if (t < C_IN) { ss[t] = 0.f; sq[t] = 0.f; }
    __syncthreads();
    atomicAdd(&ss[c0 + 0], s0); atomicAdd(&sq[c0 + 0], q0);
    atomicAdd(&ss[c0 + 1], s1); atomicAdd(&sq[c0 + 1], q1);
    atomicAdd(&ss[c0 + 2], s2); atomicAdd(&sq[c0 + 2], q2);
    atomicAdd(&ss[c0 + 3], s3); atomicAdd(&sq[c0 + 3], q3);

    for (long i = tid; i < nq; i += S) {
        int4 o = off4[i];
        int4 r = oix4[i];
        atomicAdd(&g_hist2[((r.x >> BSHIFT) << 3) + (o.x & 7)], 1);
        atomicAdd(&g_hist2[((r.y >> BSHIFT) << 3) + (o.y & 7)], 1);
        atomicAdd(&g_hist2[((r.z >> BSHIFT) << 3) + (o.z & 7)], 1);
        atomicAdd(&g_hist2[((r.w >> BSHIFT) << 3) + (o.w & 7)], 1);
    }
    if (blockIdx.x == 0 && t < (n & 3)) {
        const int* off = (const int*)off4;
        const int* oix = (const int*)oix4;
        int e = (n & ~3) + t;
        atomicAdd(&g_hist2[((oix[e] >> BSHIFT) << 3) + (off[e] & 7)], 1);
    }
    __syncthreads();
    if (t < C_IN) {
        atomicAdd(&g_sum[t], ss[t]);
        atomicAdd(&g_sq[t], sq[t]);
    }
}

// ---------------- single-block: BN finalize + full bin scan + resets ----------------
__global__ void __launch_bounds__(1024) k_scanmid(
    const float* __restrict__ gamma, const float* __restrict__ beta,
    float inv_n, int nbins) {
    __shared__ int wtot[32];
    int t = threadIdx.x;
    int lane = t & 31, wid = t >> 5;

    if (t < C_IN) {
        float mean = g_sum[t] * inv_n;
        float var  = g_sq[t] * inv_n - mean * mean;
        float sc   = gamma[t] * rsqrtf(var + 1e-5f);
        g_scale[t] = sc;
        g_shift[t] = beta[t] - mean * sc;
        g_sum[t] = 0.f;   // reset for replay
        g_sq[t]  = 0.f;
    }
    if (t == 0) g_ticket = 0;

    // 16 bins per thread, MLP-16 loads
    int b0 = t << 4;
    int h[16];
#pragma unroll
    for (int k = 0; k < 16; k++) {
        int b = b0 + k;
        h[k] = (b < nbins) ? g_hist2[b] : 0;
    }
    int s = 0;
#pragma unroll
    for (int k = 0; k < 16; k++) { int v = h[k]; h[k] = s; s += v; }

    int inc = s;
#pragma unroll
    for (int d = 1; d < 32; d <<= 1) {
        int u = __shfl_up_sync(FULLMASK, inc, d);
        if (lane >= d) inc += u;
    }
    if (lane == 31) wtot[wid] = inc;
    __syncthreads();
    if (wid == 0) {
        int x = wtot[lane];
#pragma unroll
        for (int d = 1; d < 32; d <<= 1) {
            int u = __shfl_up_sync(FULLMASK, x, d);
            if (lane >= d) x += u;
        }
        wtot[lane] = x;
    }
    __syncthreads();
    int base = (wid ? wtot[wid - 1] : 0) + inc - s;
#pragma unroll
    for (int k = 0; k < 16; k++) {
        int b = b0 + k;
        if (b < nbins) {
            int e = base + h[k];
            g_base2[b] = e;
            g_cur2[b] = e;
            g_hist2[b] = 0;   // reset for replay
        }
    }
    if (t == 1023) g_base2[nbins] = base + s;
}

// ---------------- counting-sort scatter: packed (rowlow<<21 | idx) ----------------
__global__ void k_scat(const int4* __restrict__ off4,
                       const int4* __restrict__ oix4, int nq, int n) {
    int i = blockIdx.x * blockDim.x + threadIdx.x;
    int S = gridDim.x * blockDim.x;
    for (; i < nq; i += S) {
        int4 o = off4[i];
        int4 r = oix4[i];
        int base = i << 2;
        {
            int pos = atomicAdd(&g_cur2[((r.x >> BSHIFT) << 3) + (o.x & 7)], 1);
            g_perm[pos] = ((r.x & (BROWS - 1)) << 21) | (base + 0);
        }
        {
            int pos = atomicAdd(&g_cur2[((r.y >> BSHIFT) << 3) + (o.y & 7)], 1);
            g_perm[pos] = ((r.y & (BROWS - 1)) << 21) | (base + 1);
        }
        {
            int pos = atomicAdd(&g_cur2[((r.z >> BSHIFT) << 3) + (o.z & 7)], 1);
            g_perm[pos] = ((r.z & (BROWS - 1)) << 21) | (base + 2);
        }
        {
            int pos = atomicAdd(&g_cur2[((r.w >> BSHIFT) << 3) + (o.w & 7)], 1);
            g_perm[pos] = ((r.w & (BROWS - 1)) << 21) | (base + 3);
        }
    }
    if (blockIdx.x == 0 && threadIdx.x < (n & 3)) {
        const int* off = (const int*)off4;
        const int* oix = (const int*)oix4;
        int e = (n & ~3) + threadIdx.x;
        int row = oix[e];
        int pos = atomicAdd(&g_cur2[((row >> BSHIFT) << 3) + (off[e] & 7)], 1);
        g_perm[pos] = ((row & (BROWS - 1)) << 21) | e;
    }
}

// ---------------- main conv: ticketed CTA-per-bucket, warp = tap ----------------
__global__ void __launch_bounds__(256, 2)
k_conv(const float* __restrict__ f, const float* __restrict__ weight,
       float* __restrict__ out, int nb, int nrows) {
    __shared__ float sv[8][2][BATCH][C_IN];
    __shared__ int sb;
    int lane = threadIdx.x & 31;
    int wl = threadIdx.x >> 5;          // warp id == tap id

    // tap weights, channel-paired
    unsigned long long w0[16], w1[16];
    {
        const float* wp = weight + (wl * C_IN) * C_OUT;
#pragma unroll
        for (int k = 0; k < 16; k++) {
            w0[k] = pk(wp[(2 * k) * C_OUT + 2 * lane],
                       wp[(2 * k + 1) * C_OUT + 2 * lane]);
            w1[k] = pk(wp[(2 * k) * C_OUT + 2 * lane + 1],
                       wp[(2 * k + 1) * C_OUT + 2 * lane + 1]);
        }
    }
    float sc = g_scale[lane];
    float sh = g_shift[lane];

    while (true) {
        if (threadIdx.x == 0) sb = atomicAdd(&g_ticket, 1);
        __syncthreads();
        int b = sb;
        if (b >= nb) break;

        // zero this bucket's output region (lines stay dirty in L2 for atomics)
        long r0 = (long)b << BSHIFT;
        long r1 = min((long)nrows, r0 + (long)BROWS);
        float4* oz = (float4*)(out + r0 * C_OUT);
        long n4 = (r1 - r0) * (C_OUT / 4);
        float4 z = make_float4(0.f, 0.f, 0.f, 0.f);
        for (long i = threadIdx.x; i < n4; i += 256) oz[i] = z;
        __syncthreads();

        int bin = (b << 3) + wl;
        int j = g_base2[bin];
        int j1 = g_base2[bin + 1];
        int rbase = b << BSHIFT;

        // ---- prologue: words(k), words(k+1), features(k) ----
        int m = min(BATCH, j1 - j);
        int wc[BATCH], wn[BATCH], wn2[BATCH];
        float x[BATCH];
#pragma unroll
        for (int t = 0; t < BATCH; t++)
            if (t < m) wc[t] = g_perm[j + t];
        int jn = j + m;
        int mn = min(BATCH, j1 - jn);
#pragma unroll
        for (int t = 0; t < BATCH; t++)
            if (t < mn) wn[t] = g_perm[jn + t];
#pragma unroll
        for (int t = 0; t < BATCH; t++)
            if (t < m) x[t] = f[((long)(wc[t] & IDXMASK) << 5) + lane];

        int it = 0;
        while (j < j1) {
            int buf = it & 1;
#pragma unroll
            for (int t = 0; t < BATCH; t++)
                if (t < m) sv[wl][buf][t][lane] = fmaxf(fmaf(x[t], sc, sh), 0.f);
            __syncwarp();

            // features(k+1) from resident words(k+1)
#pragma unroll
            for (int t = 0; t < BATCH; t++)
                if (t < mn) x[t] = f[((long)(wn[t] & IDXMASK) << 5) + lane];

            // words(k+2)
            int jn2 = jn + mn;
            int mn2 = min(BATCH, j1 - jn2);
#pragma unroll
            for (int t = 0; t < BATCH; t++)
                if (t < mn2) wn2[t] = g_perm[jn2 + t];

            // compute + reduce batch k
#pragma unroll
            for (int t = 0; t < BATCH; t++)
                if (t < m) {
                    const ulonglong2* vp = (const ulonglong2*)&sv[wl][buf][t][0];
                    unsigned long long a0 = 0ull, a1 = 0ull;
#pragma unroll
                    for (int k = 0; k < 8; k++) {
                        ulonglong2 q = vp[k];
                        a0 = fma2(q.x, w0[2 * k], a0);
                        a1 = fma2(q.x, w1[2 * k], a1);
                        a0 = fma2(q.y, w0[2 * k + 1], a0);
                        a1 = fma2(q.y, w1[2 * k + 1], a1);
                    }
                    float e0, o0, e1, o1;
                    upk(a0, e0, o0);
                    upk(a1, e1, o1);
                    int row = rbase + (wc[t] >> 21);
                    red_add_v2(out + ((long)row << 6) + (lane << 1),
                               e0 + o0, e1 + o1);
                }
#pragma unroll
            for (int t = 0; t < BATCH; t++) { wc[t] = wn[t]; wn[t] = wn2[t]; }
            j = jn; m = mn; jn = jn2; mn = mn2;
            it++;
        }
        __syncthreads();   // protect sb before next ticket
    }
}

// ---------------- launch ----------------
extern "C" void kernel_launch(void* const* d_in, const int* in_sizes, int n_in,
                              void* d_out, int out_size) {
    const float* features = (const float*)d_in[0];
    const float* gamma    = (const float*)d_in[1];
    const float* beta     = (const float*)d_in[2];
    const float* weight   = (const float*)d_in[3];
    const int* out_index  = (const int*)d_in[4];
    const int* off_index  = (const int*)d_in[5];

    int n = in_sizes[0] / C_IN;
    int nq = n >> 2;
    int nrows = out_size / C_OUT;
    int nb = (nrows + BROWS - 1) >> BSHIFT;
    int nbins = nb * 8;

    k_pre<<<1184, 256>>>((const float4*)features, (long)n * C_IN / 4,
                         (const int4*)off_index, (const int4*)out_index, nq, n);
    k_scanmid<<<1, 1024>>>(gamma, beta, 1.0f / (float)n, nbins);
    k_scat<<<1184, 256>>>((const int4*)off_index, (const int4*)out_index, nq, n);
    k_conv<<<296, 256>>>(features, weight, (float*)d_out, nb, nrows);
}